// round 2
// baseline (speedup 1.0000x reference)
#include <cuda_runtime.h>
#include <cuda_bf16.h>
#include <cstdint>

#define NN 100000
#define EE 800000
#define HEADS 8
#define CH 16
#define DIM 128
#define NEG_SLOPE 0.2f

// ---------------- scratch (device globals; no allocation allowed) -------------
__device__ float g_h_in[NN * DIM];
__device__ float g_h_out[NN * DIM];
__device__ float g_asrc_in[NN * HEADS];
__device__ float g_adst_in[NN * HEADS];
__device__ float g_asrc_out[NN * HEADS];
__device__ float g_adst_out[NN * HEADS];
__device__ float g_den_in[NN * HEADS];
__device__ float g_den_out[NN * HEADS];

// ---------------- helpers ------------------------------------------------------
__device__ __forceinline__ void red_add_v4(float* p, float a, float b, float c, float d) {
    asm volatile("red.global.add.v4.f32 [%0], {%1, %2, %3, %4};"
                 :: "l"(p), "f"(a), "f"(b), "f"(c), "f"(d) : "memory");
}

__device__ __forceinline__ float lrelu(float v) {
    return v > 0.0f ? v : NEG_SLOPE * v;
}

// ---------------- init kernels -------------------------------------------------
__global__ void init_out_kernel(float* __restrict__ out,
                                const float* __restrict__ b_in,
                                const float* __restrict__ b_out) {
    int t = blockIdx.x * blockDim.x + threadIdx.x;
    if (t >= NN * DIM) return;
    int c = t & (DIM - 1);
    out[t] = b_in[c] + b_out[c];
}

__global__ void zero_denoms_kernel() {
    int t = blockIdx.x * blockDim.x + threadIdx.x;
    if (t >= NN * HEADS) return;
    g_den_in[t] = 0.0f;
    g_den_out[t] = 0.0f;
}

// ---------------- GEMM: C[M,128] = A[M,128] @ B[128,128] ------------------------
// BM=128, BN=128, BK=16, 256 threads, 8x8 micro-tile per thread.
__global__ __launch_bounds__(256, 2)
void gemm128_kernel(const float* __restrict__ A, const float* __restrict__ B,
                    float* __restrict__ C, int M) {
    __shared__ float As[16][128];   // [k][m] (transposed)
    __shared__ float Bs[16][128];   // [k][n]

    int tid = threadIdx.x;
    int tx = tid & 15;       // 0..15 -> cols
    int ty = tid >> 4;       // 0..15 -> rows
    int row0 = blockIdx.x * 128;

    float acc[8][8];
#pragma unroll
    for (int i = 0; i < 8; i++)
#pragma unroll
        for (int j = 0; j < 8; j++) acc[i][j] = 0.0f;

    for (int k0 = 0; k0 < 128; k0 += 16) {
        // load A tile 128x16 (2048 floats, 2 float4 per thread)
        int ar = tid >> 2;
        int ac = (tid & 3) * 4;
#pragma unroll
        for (int rr = 0; rr < 2; rr++) {
            int r = ar + rr * 64;
            float4 v = make_float4(0.f, 0.f, 0.f, 0.f);
            if (row0 + r < M)
                v = *(const float4*)&A[(size_t)(row0 + r) * DIM + k0 + ac];
            As[ac + 0][r] = v.x;
            As[ac + 1][r] = v.y;
            As[ac + 2][r] = v.z;
            As[ac + 3][r] = v.w;
        }
        // load B tile 16x128
        int br = tid >> 5;
        int bc = (tid & 31) * 4;
#pragma unroll
        for (int rr = 0; rr < 2; rr++) {
            int r = br + rr * 8;
            *(float4*)&Bs[r][bc] = *(const float4*)&B[(size_t)(k0 + r) * DIM + bc];
        }
        __syncthreads();

#pragma unroll
        for (int k = 0; k < 16; k++) {
            float a[8], b[8];
#pragma unroll
            for (int i = 0; i < 8; i++) a[i] = As[k][ty * 8 + i];
#pragma unroll
            for (int j = 0; j < 8; j++) b[j] = Bs[k][tx * 8 + j];
#pragma unroll
            for (int i = 0; i < 8; i++)
#pragma unroll
                for (int j = 0; j < 8; j++) acc[i][j] += a[i] * b[j];
        }
        __syncthreads();
    }

#pragma unroll
    for (int i = 0; i < 8; i++) {
        int r = row0 + ty * 8 + i;
        if (r < M) {
#pragma unroll
            for (int j = 0; j < 8; j += 4) {
                *(float4*)&C[(size_t)r * DIM + tx * 8 + j] =
                    make_float4(acc[i][j], acc[i][j + 1], acc[i][j + 2], acc[i][j + 3]);
            }
        }
    }
}

// ---------------- per-node attention logits ------------------------------------
// thread t -> (node n, head h); dot of 16 channels with each attention vector.
__global__ void alpha_kernel(const float* __restrict__ a_src_in,
                             const float* __restrict__ a_dst_in,
                             const float* __restrict__ a_src_out,
                             const float* __restrict__ a_dst_out) {
    int t = blockIdx.x * blockDim.x + threadIdx.x;
    if (t >= NN * HEADS) return;
    int n = t >> 3;
    int hd = t & 7;

    const float4* hi = (const float4*)&g_h_in[(size_t)n * DIM + hd * CH];
    const float4* ho = (const float4*)&g_h_out[(size_t)n * DIM + hd * CH];
    const float4* wsi = (const float4*)&a_src_in[hd * CH];
    const float4* wdi = (const float4*)&a_dst_in[hd * CH];
    const float4* wso = (const float4*)&a_src_out[hd * CH];
    const float4* wdo = (const float4*)&a_dst_out[hd * CH];

    float si = 0.f, di = 0.f, so = 0.f, dof = 0.f;
#pragma unroll
    for (int q = 0; q < 4; q++) {
        float4 v = hi[q];
        float4 w1 = wsi[q];
        float4 w2 = wdi[q];
        si += v.x * w1.x + v.y * w1.y + v.z * w1.z + v.w * w1.w;
        di += v.x * w2.x + v.y * w2.y + v.z * w2.z + v.w * w2.w;
        float4 u = ho[q];
        float4 w3 = wso[q];
        float4 w4 = wdo[q];
        so += u.x * w3.x + u.y * w3.y + u.z * w3.z + u.w * w3.w;
        dof += u.x * w4.x + u.y * w4.y + u.z * w4.z + u.w * w4.w;
    }
    g_asrc_in[t] = si;
    g_adst_in[t] = di;
    g_asrc_out[t] = so;
    g_adst_out[t] = dof;
}

// ---------------- softmax denominators (shift-invariant: no segment_max) --------
// thread t -> (edge e, head h).
__global__ void denom_kernel(const int* __restrict__ ei) {
    int t = blockIdx.x * blockDim.x + threadIdx.x;
    if (t >= EE * HEADS) return;
    int e = t >> 3;
    int hd = t & 7;
    int s = __ldg(&ei[e]);
    int d = __ldg(&ei[EE + e]);

    // in-direction: messages flow s -> d (softmax grouped by d)
    float li = lrelu(g_asrc_in[s * HEADS + hd] + g_adst_in[d * HEADS + hd]);
    atomicAdd(&g_den_in[d * HEADS + hd], __expf(li));

    // out-direction: flipped edges, messages flow d -> s (grouped by s)
    float lo = lrelu(g_asrc_out[d * HEADS + hd] + g_adst_out[s * HEADS + hd]);
    atomicAdd(&g_den_out[s * HEADS + hd], __expf(lo));
}

// ---------------- aggregation: warp per edge, both directions -------------------
__global__ __launch_bounds__(256)
void agg_kernel(const int* __restrict__ ei, float* __restrict__ out) {
    int gt = blockIdx.x * blockDim.x + threadIdx.x;
    int e = gt >> 5;
    if (e >= EE) return;
    int lane = threadIdx.x & 31;
    int hd = lane >> 2;           // head for this lane's 4 channels
    int s = __ldg(&ei[e]);
    int d = __ldg(&ei[EE + e]);

    // in-direction coefficient for (e, hd)
    float li = lrelu(g_asrc_in[s * HEADS + hd] + g_adst_in[d * HEADS + hd]);
    float coef_in = __expf(li) / g_den_in[d * HEADS + hd];

    // out-direction coefficient for (flipped e, hd)
    float lo = lrelu(g_asrc_out[d * HEADS + hd] + g_adst_out[s * HEADS + hd]);
    float coef_out = __expf(lo) / g_den_out[s * HEADS + hd];

    int c4 = lane * 4;
    float4 hi = *(const float4*)&g_h_in[(size_t)s * DIM + c4];
    float4 ho = *(const float4*)&g_h_out[(size_t)d * DIM + c4];

    red_add_v4(&out[(size_t)d * DIM + c4],
               hi.x * coef_in, hi.y * coef_in, hi.z * coef_in, hi.w * coef_in);
    red_add_v4(&out[(size_t)s * DIM + c4],
               ho.x * coef_out, ho.y * coef_out, ho.z * coef_out, ho.w * coef_out);
}

// ---------------- launch --------------------------------------------------------
extern "C" void kernel_launch(void* const* d_in, const int* in_sizes, int n_in,
                              void* d_out, int out_size) {
    const float* x        = (const float*)d_in[0];
    const int*   ei       = (const int*)d_in[1];
    const float* W_in     = (const float*)d_in[2];
    const float* a_src_in = (const float*)d_in[3];
    const float* a_dst_in = (const float*)d_in[4];
    const float* b_in     = (const float*)d_in[5];
    const float* W_out    = (const float*)d_in[6];
    const float* a_src_out= (const float*)d_in[7];
    const float* a_dst_out= (const float*)d_in[8];
    const float* b_out    = (const float*)d_in[9];
    float* out = (float*)d_out;

    float* h_in;
    float* h_out;
    cudaGetSymbolAddress((void**)&h_in, g_h_in);
    cudaGetSymbolAddress((void**)&h_out, g_h_out);

    // init output with biases; zero softmax denominators
    init_out_kernel<<<(NN * DIM + 255) / 256, 256>>>(out, b_in, b_out);
    zero_denoms_kernel<<<(NN * HEADS + 255) / 256, 256>>>();

    // projections
    gemm128_kernel<<<(NN + 127) / 128, 256>>>(x, W_in, h_in, NN);
    gemm128_kernel<<<(NN + 127) / 128, 256>>>(x, W_out, h_out, NN);

    // per-node logits
    alpha_kernel<<<(NN * HEADS + 255) / 256, 256>>>(a_src_in, a_dst_in, a_src_out, a_dst_out);

    // softmax denominators (one edge pass, both directions)
    denom_kernel<<<(EE * HEADS + 255) / 256, 256>>>(ei);

    // weighted aggregation (one edge pass, both directions)
    agg_kernel<<<(EE * 32 + 255) / 256, 256>>>(ei, out);
}

// round 3
// speedup vs baseline: 1.0006x; 1.0006x over previous
#include <cuda_runtime.h>
#include <cuda_bf16.h>
#include <cstdint>

#define NN 100000
#define EE 800000
#define HEADS 8
#define CH 16
#define DIM 128
#define NEG_SLOPE 0.2f

// ---------------- scratch (device globals; no allocation allowed) -------------
__device__ float g_h_in[NN * DIM];
__device__ float g_h_out[NN * DIM];
__device__ float g_asrc_in[NN * HEADS];
__device__ float g_adst_in[NN * HEADS];
__device__ float g_asrc_out[NN * HEADS];
__device__ float g_adst_out[NN * HEADS];
__device__ float g_den_in[NN * HEADS];
__device__ float g_den_out[NN * HEADS];

// ---------------- helpers ------------------------------------------------------
__device__ __forceinline__ void red_add_v4(float* p, float a, float b, float c, float d) {
    asm volatile("red.global.add.v4.f32 [%0], {%1, %2, %3, %4};"
                 :: "l"(p), "f"(a), "f"(b), "f"(c), "f"(d) : "memory");
}

__device__ __forceinline__ float lrelu(float v) {
    return v > 0.0f ? v : NEG_SLOPE * v;
}

// ---------------- init kernels -------------------------------------------------
__global__ void init_out_kernel(float* __restrict__ out,
                                const float* __restrict__ b_in,
                                const float* __restrict__ b_out) {
    int t = blockIdx.x * blockDim.x + threadIdx.x;
    if (t >= NN * DIM) return;
    int c = t & (DIM - 1);
    out[t] = b_in[c] + b_out[c];
}

__global__ void zero_denoms_kernel() {
    int t = blockIdx.x * blockDim.x + threadIdx.x;
    if (t >= NN * HEADS) return;
    g_den_in[t] = 0.0f;
    g_den_out[t] = 0.0f;
}

// ---------------- GEMM: C[M,128] = A[M,128] @ B[128,128] ------------------------
// BM=128, BN=128, BK=16, 256 threads, 8x8 micro-tile per thread.
__global__ __launch_bounds__(256, 2)
void gemm128_kernel(const float* __restrict__ A, const float* __restrict__ B,
                    float* __restrict__ C, int M) {
    __shared__ float As[16][128];   // [k][m] (transposed)
    __shared__ float Bs[16][128];   // [k][n]

    int tid = threadIdx.x;
    int tx = tid & 15;       // 0..15 -> cols
    int ty = tid >> 4;       // 0..15 -> rows
    int row0 = blockIdx.x * 128;

    float acc[8][8];
#pragma unroll
    for (int i = 0; i < 8; i++)
#pragma unroll
        for (int j = 0; j < 8; j++) acc[i][j] = 0.0f;

    for (int k0 = 0; k0 < 128; k0 += 16) {
        // load A tile 128x16 (2048 floats, 2 float4 per thread)
        int ar = tid >> 2;
        int ac = (tid & 3) * 4;
#pragma unroll
        for (int rr = 0; rr < 2; rr++) {
            int r = ar + rr * 64;
            float4 v = make_float4(0.f, 0.f, 0.f, 0.f);
            if (row0 + r < M)
                v = *(const float4*)&A[(size_t)(row0 + r) * DIM + k0 + ac];
            As[ac + 0][r] = v.x;
            As[ac + 1][r] = v.y;
            As[ac + 2][r] = v.z;
            As[ac + 3][r] = v.w;
        }
        // load B tile 16x128
        int br = tid >> 5;
        int bc = (tid & 31) * 4;
#pragma unroll
        for (int rr = 0; rr < 2; rr++) {
            int r = br + rr * 8;
            *(float4*)&Bs[r][bc] = *(const float4*)&B[(size_t)(k0 + r) * DIM + bc];
        }
        __syncthreads();

#pragma unroll
        for (int k = 0; k < 16; k++) {
            float a[8], b[8];
#pragma unroll
            for (int i = 0; i < 8; i++) a[i] = As[k][ty * 8 + i];
#pragma unroll
            for (int j = 0; j < 8; j++) b[j] = Bs[k][tx * 8 + j];
#pragma unroll
            for (int i = 0; i < 8; i++)
#pragma unroll
                for (int j = 0; j < 8; j++) acc[i][j] += a[i] * b[j];
        }
        __syncthreads();
    }

#pragma unroll
    for (int i = 0; i < 8; i++) {
        int r = row0 + ty * 8 + i;
        if (r < M) {
#pragma unroll
            for (int j = 0; j < 8; j += 4) {
                *(float4*)&C[(size_t)r * DIM + tx * 8 + j] =
                    make_float4(acc[i][j], acc[i][j + 1], acc[i][j + 2], acc[i][j + 3]);
            }
        }
    }
}

// ---------------- per-node attention logits ------------------------------------
// thread t -> (node n, head h); dot of 16 channels with each attention vector.
__global__ void alpha_kernel(const float* __restrict__ a_src_in,
                             const float* __restrict__ a_dst_in,
                             const float* __restrict__ a_src_out,
                             const float* __restrict__ a_dst_out) {
    int t = blockIdx.x * blockDim.x + threadIdx.x;
    if (t >= NN * HEADS) return;
    int n = t >> 3;
    int hd = t & 7;

    const float4* hi = (const float4*)&g_h_in[(size_t)n * DIM + hd * CH];
    const float4* ho = (const float4*)&g_h_out[(size_t)n * DIM + hd * CH];
    const float4* wsi = (const float4*)&a_src_in[hd * CH];
    const float4* wdi = (const float4*)&a_dst_in[hd * CH];
    const float4* wso = (const float4*)&a_src_out[hd * CH];
    const float4* wdo = (const float4*)&a_dst_out[hd * CH];

    float si = 0.f, di = 0.f, so = 0.f, dof = 0.f;
#pragma unroll
    for (int q = 0; q < 4; q++) {
        float4 v = hi[q];
        float4 w1 = wsi[q];
        float4 w2 = wdi[q];
        si += v.x * w1.x + v.y * w1.y + v.z * w1.z + v.w * w1.w;
        di += v.x * w2.x + v.y * w2.y + v.z * w2.z + v.w * w2.w;
        float4 u = ho[q];
        float4 w3 = wso[q];
        float4 w4 = wdo[q];
        so += u.x * w3.x + u.y * w3.y + u.z * w3.z + u.w * w3.w;
        dof += u.x * w4.x + u.y * w4.y + u.z * w4.z + u.w * w4.w;
    }
    g_asrc_in[t] = si;
    g_adst_in[t] = di;
    g_asrc_out[t] = so;
    g_adst_out[t] = dof;
}

// ---------------- softmax denominators (shift-invariant: no segment_max) --------
// thread t -> (edge e, head h).
__global__ void denom_kernel(const int* __restrict__ ei) {
    int t = blockIdx.x * blockDim.x + threadIdx.x;
    if (t >= EE * HEADS) return;
    int e = t >> 3;
    int hd = t & 7;
    int s = __ldg(&ei[e]);
    int d = __ldg(&ei[EE + e]);

    // in-direction: messages flow s -> d (softmax grouped by d)
    float li = lrelu(g_asrc_in[s * HEADS + hd] + g_adst_in[d * HEADS + hd]);
    atomicAdd(&g_den_in[d * HEADS + hd], __expf(li));

    // out-direction: flipped edges, messages flow d -> s (grouped by s)
    float lo = lrelu(g_asrc_out[d * HEADS + hd] + g_adst_out[s * HEADS + hd]);
    atomicAdd(&g_den_out[s * HEADS + hd], __expf(lo));
}

// ---------------- aggregation: warp per edge, both directions -------------------
__global__ __launch_bounds__(256)
void agg_kernel(const int* __restrict__ ei, float* __restrict__ out) {
    int gt = blockIdx.x * blockDim.x + threadIdx.x;
    int e = gt >> 5;
    if (e >= EE) return;
    int lane = threadIdx.x & 31;
    int hd = lane >> 2;           // head for this lane's 4 channels
    int s = __ldg(&ei[e]);
    int d = __ldg(&ei[EE + e]);

    // in-direction coefficient for (e, hd)
    float li = lrelu(g_asrc_in[s * HEADS + hd] + g_adst_in[d * HEADS + hd]);
    float coef_in = __expf(li) / g_den_in[d * HEADS + hd];

    // out-direction coefficient for (flipped e, hd)
    float lo = lrelu(g_asrc_out[d * HEADS + hd] + g_adst_out[s * HEADS + hd]);
    float coef_out = __expf(lo) / g_den_out[s * HEADS + hd];

    int c4 = lane * 4;
    float4 hi = *(const float4*)&g_h_in[(size_t)s * DIM + c4];
    float4 ho = *(const float4*)&g_h_out[(size_t)d * DIM + c4];

    red_add_v4(&out[(size_t)d * DIM + c4],
               hi.x * coef_in, hi.y * coef_in, hi.z * coef_in, hi.w * coef_in);
    red_add_v4(&out[(size_t)s * DIM + c4],
               ho.x * coef_out, ho.y * coef_out, ho.z * coef_out, ho.w * coef_out);
}

// ---------------- launch --------------------------------------------------------
extern "C" void kernel_launch(void* const* d_in, const int* in_sizes, int n_in,
                              void* d_out, int out_size) {
    const float* x        = (const float*)d_in[0];
    const int*   ei       = (const int*)d_in[1];
    const float* W_in     = (const float*)d_in[2];
    const float* a_src_in = (const float*)d_in[3];
    const float* a_dst_in = (const float*)d_in[4];
    const float* b_in     = (const float*)d_in[5];
    const float* W_out    = (const float*)d_in[6];
    const float* a_src_out= (const float*)d_in[7];
    const float* a_dst_out= (const float*)d_in[8];
    const float* b_out    = (const float*)d_in[9];
    float* out = (float*)d_out;

    float* h_in;
    float* h_out;
    cudaGetSymbolAddress((void**)&h_in, g_h_in);
    cudaGetSymbolAddress((void**)&h_out, g_h_out);

    // init output with biases; zero softmax denominators
    init_out_kernel<<<(NN * DIM + 255) / 256, 256>>>(out, b_in, b_out);
    zero_denoms_kernel<<<(NN * HEADS + 255) / 256, 256>>>();

    // projections
    gemm128_kernel<<<(NN + 127) / 128, 256>>>(x, W_in, h_in, NN);
    gemm128_kernel<<<(NN + 127) / 128, 256>>>(x, W_out, h_out, NN);

    // per-node logits
    alpha_kernel<<<(NN * HEADS + 255) / 256, 256>>>(a_src_in, a_dst_in, a_src_out, a_dst_out);

    // softmax denominators (one edge pass, both directions)
    denom_kernel<<<(EE * HEADS + 255) / 256, 256>>>(ei);

    // weighted aggregation (one edge pass, both directions)
    agg_kernel<<<(EE * 32 + 255) / 256, 256>>>(ei, out);
}